// round 14
// baseline (speedup 1.0000x reference)
#include <cuda_runtime.h>
#include <cuda_fp16.h>
#include <math.h>
#include <stdint.h>

#define T_ 64
#define B_ 64
#define V_ 32000
#define E_ 512
#define H_ 1024
#define CTX_ 1024
#define FOURH 4096
#define M_ (T_*B_)
#define RC 128

// ---------------- device scratch ----------------
__device__ __align__(256) float g_c[B_*H_];
__device__ __align__(256) float g_gctx[B_*FOURH];
__device__ __align__(256) unsigned g_bar1[8*32];
__device__ unsigned g_bar2;

__device__ __align__(256) __half g_embg[M_*FOURH];
__device__ __align__(256) __half g_hbuf[2][B_*H_];
__device__ __align__(256) __half g_xe[M_*E_];
__device__ __align__(256) __half g_wihe[FOURH*E_];
__device__ __align__(256) __half g_wd1[H_*2*H_];
__device__ __align__(256) __half g_wd2[(size_t)V_*H_];
__device__ __align__(256) __half g_hcat[M_*2*H_];
__device__ __align__(256) __half g_hid[M_*H_];

__device__ __forceinline__ float sigf(float x){ return 1.f/(1.f+__expf(-x)); }

__device__ __forceinline__ uint32_t smem_u32(const void* p) {
    uint32_t a;
    asm("{ .reg .u64 t; cvta.to.shared.u64 t, %1; cvt.u32.u64 %0, t; }" : "=r"(a) : "l"(p));
    return a;
}
__device__ __forceinline__ void cp_async16(uint32_t dst, const void* src){
    asm volatile("cp.async.cg.shared.global [%0], [%1], 16;\n" :: "r"(dst), "l"(src));
}
__device__ __forceinline__ void cp_commit(){
    asm volatile("cp.async.commit_group;\n" ::: "memory");
}
template<int N> __device__ __forceinline__ void cp_wait(){
    asm volatile("cp.async.wait_group %0;\n" :: "n"(N) : "memory");
}
__device__ __forceinline__ void ldsm4(uint32_t& r0,uint32_t& r1,uint32_t& r2,uint32_t& r3,
                                      uint32_t addr){
    asm volatile("ldmatrix.sync.aligned.m8n8.x4.shared.b16 {%0,%1,%2,%3}, [%4];\n"
        : "=r"(r0),"=r"(r1),"=r"(r2),"=r"(r3) : "r"(addr));
}
__device__ __forceinline__ void mma16816(float* d, const uint32_t* a, uint32_t b0, uint32_t b1){
    asm volatile("mma.sync.aligned.m16n8k16.row.col.f32.f16.f16.f32 "
        "{%0,%1,%2,%3}, {%4,%5,%6,%7}, {%8,%9}, {%0,%1,%2,%3};\n"
        : "+f"(d[0]),"+f"(d[1]),"+f"(d[2]),"+f"(d[3])
        : "r"(a[0]),"r"(a[1]),"r"(a[2]),"r"(a[3]), "r"(b0),"r"(b1));
}

// ---- fused prep: embedding gather + all fp32->fp16 weight conversions ----
__global__ void prep_kernel(const int* __restrict__ seq, const float* __restrict__ emb,
                            const float* __restrict__ W_ih, const float* __restrict__ W_d1,
                            const float* __restrict__ W_d2){
    int bid = blockIdx.x;
    const float* src; int cols; __half* dst; size_t drow;
    if (bid < M_){
        int tok = __ldg(seq + bid);
        src = emb + (size_t)tok*E_; cols = E_;
        dst = g_xe; drow = (size_t)bid*E_;
    } else if (bid < M_ + FOURH){
        int r = bid - M_;
        src = W_ih + (size_t)r*(E_+CTX_) + CTX_; cols = E_;
        dst = g_wihe; drow = (size_t)r*E_;
    } else if (bid < M_ + FOURH + H_){
        int r = bid - M_ - FOURH;
        src = W_d1 + (size_t)r*(2*H_); cols = 2*H_;
        dst = g_wd1; drow = (size_t)r*(2*H_);
    } else {
        int r = bid - M_ - FOURH - H_;
        src = W_d2 + (size_t)r*H_; cols = H_;
        dst = g_wd2; drow = (size_t)r*H_;
    }
    const float4* s = (const float4*)src;
    for (int c4 = threadIdx.x; c4*4 < cols; c4 += blockDim.x){
        float4 v = s[c4];
        __half2 p0, p1;
        p0.x = __float2half(v.x); p0.y = __float2half(v.y);
        p1.x = __float2half(v.z); p1.y = __float2half(v.w);
        *(__half2*)(dst + drow + c4*4)     = p0;
        *(__half2*)(dst + drow + c4*4 + 2) = p1;
    }
}

// ---------------- fused init GEMM: h0, c0, gctx in one launch ----------------
__global__ __launch_bounds__(256) void init_gemm(
    const float* __restrict__ A,
    const float* __restrict__ W_initS, const float* __restrict__ b_initS,
    const float* __restrict__ W_initC, const float* __restrict__ b_initC,
    const float* __restrict__ W_ih,    const float* __restrict__ b_ih,
    const float* __restrict__ b_hh)
{
  int tid = threadIdx.x;
  int ny = blockIdx.x;
  if (ny == 0 && tid < 8) g_bar1[tid*32] = 0u;
  if (ny == 0 && tid == 0) g_bar2 = 0u;

  const float* W; int ldw; int cls; int nbase;
  if (ny < 16)      { W = W_initS + (size_t)ny*64*CTX_;           ldw = CTX_;      cls = 0; nbase = ny*64; }
  else if (ny < 32) { W = W_initC + (size_t)(ny-16)*64*CTX_;      ldw = CTX_;      cls = 1; nbase = (ny-16)*64; }
  else              { W = W_ih   + (size_t)(ny-32)*64*(E_+CTX_);  ldw = E_+CTX_;   cls = 2; nbase = (ny-32)*64; }

  __shared__ __align__(16) float As[16][68];
  __shared__ __align__(16) float Ws[16][68];
  int r = tid>>2, c4 = tid&3;
  int tx = tid&15, ty = tid>>4;
  float acc[4][4] = {};
  for (int k0=0;k0<CTX_;k0+=16){
    float4 av = *(const float4*)(A + (size_t)r*CTX_ + k0 + c4*4);
    float4 wv = *(const float4*)(W + (size_t)r*ldw + k0 + c4*4);
    As[c4*4+0][r]=av.x; As[c4*4+1][r]=av.y; As[c4*4+2][r]=av.z; As[c4*4+3][r]=av.w;
    Ws[c4*4+0][r]=wv.x; Ws[c4*4+1][r]=wv.y; Ws[c4*4+2][r]=wv.z; Ws[c4*4+3][r]=wv.w;
    __syncthreads();
#pragma unroll
    for (int kk=0;kk<16;kk++){
      float4 a = *(const float4*)&As[kk][ty*4];
      float4 w = *(const float4*)&Ws[kk][tx*4];
      float aa[4]={a.x,a.y,a.z,a.w}, ww[4]={w.x,w.y,w.z,w.w};
#pragma unroll
      for (int i=0;i<4;i++)
#pragma unroll
        for (int j=0;j<4;j++) acc[i][j] += aa[i]*ww[j];
    }
    __syncthreads();
  }
#pragma unroll
  for (int i=0;i<4;i++){
    int m = ty*4 + i;
#pragma unroll
    for (int j=0;j<4;j++){
      int n = nbase + tx*4 + j;
      float v = acc[i][j];
      if (cls == 0){
        v = tanhf(v + b_initS[n]);
        g_hbuf[0][m*H_ + n] = __float2half(v);
      } else if (cls == 1){
        v = tanhf(v + b_initC[n]);
        g_c[m*H_ + n] = v;
      } else {
        g_gctx[m*FOURH + n] = v + b_ih[n] + b_hh[n];
      }
    }
  }
}

// ---------------- persistent recurrence kernel ----------------
#define WPITCH 1032
#define HPITCH 520
#define OFF_W   0
#define OFF_H   (32*WPITCH*2)
#define OFF_GT  (OFF_H + 2*64*HPITCH*2)
#define OFF_GC  (OFF_GT + 64*36*4)
#define OFF_C   (OFF_GC + 64*32*4)
#define OFF_EB  (OFF_C + 512*4)
#define REC_SMEM (OFF_EB + 64*40*2)

__global__ __launch_bounds__(256,1) void rec_kernel(const float* __restrict__ W_hh){
    extern __shared__ char sm[];
    uint32_t sbase = smem_u32(sm);
    float*  sGT = (float*) (sm + OFF_GT);
    float*  sGC = (float*) (sm + OFF_GC);
    float*  sC  = (float*) (sm + OFF_C);
    __half* sEB = (__half*)(sm + OFF_EB);
    uint32_t hU = sbase + OFF_H;
    uint32_t ebU = sbase + OFF_EB;

    int tid = threadIdx.x;
    int lane = tid & 31, wid = tid >> 5;
    int s = blockIdx.x;
    int js0 = s * 8;

    // W_hh slice: load fp32, convert, store to smem
    for (int q = tid; q < 4096; q += 256){
        int row = q >> 7, cc = q & 127;
        int grow = (row >> 3)*H_ + js0 + (row & 7);
        const float4* src = (const float4*)(W_hh + (size_t)grow*H_ + cc*8);
        float4 v0 = src[0], v1 = src[1];
        __half h[8];
        h[0]=__float2half(v0.x); h[1]=__float2half(v0.y);
        h[2]=__float2half(v0.z); h[3]=__float2half(v0.w);
        h[4]=__float2half(v1.x); h[5]=__float2half(v1.y);
        h[6]=__float2half(v1.z); h[7]=__float2half(v1.w);
        *(uint4*)(sm + OFF_W + (size_t)(row*WPITCH + cc*8)*2) = *(uint4*)h;
    }
    for (int e = tid; e < 2048; e += 256){
        int b = e >> 5, n = e & 31;
        sGC[b*32 + n] = g_gctx[b*FOURH + (n>>3)*H_ + js0 + (n&7)];
    }
    for (int e = tid; e < 512; e += 256)
        sC[e] = g_c[(e>>3)*H_ + js0 + (e&7)];
    __syncthreads();

    int quad = lane >> 3, l7 = lane & 7;
    int mi = wid & 3, nh = wid >> 2;
    int arow = mi*16 + (quad & 1)*8 + l7;
    int acol = (quad >> 1)*8;
    int brow = nh*16 + (quad >> 1)*8 + l7;
    int bcol = (quad & 1)*8;
    int rin = lane >> 2, cin = (lane & 3)*2;

    int pb = tid >> 2, pg = tid & 3;
    int gidx = s & 7;

    for (int t = 0; t < T_; t++){
        const __half* hsrc = g_hbuf[t & 1];

        float acc[2][4];
#pragma unroll
        for (int a=0;a<2;a++)
#pragma unroll
          for (int q=0;q<4;q++) acc[a][q]=0.f;

        // prefetch embg strip (group 0)
        cp_async16(ebU + (uint32_t)(pb*40 + pg*8)*2,
                   g_embg + ((size_t)(t*B_ + pb))*FOURH + pg*H_ + js0);
        cp_commit();

        auto issueH = [&](int kc){
            uint32_t dU = hU + (uint32_t)((kc & 1)*64*HPITCH)*2;
#pragma unroll
            for (int i = 0; i < 16; i++){
                int q = i*256 + tid;
                int row = q >> 6, cc = q & 63;
                cp_async16(dU + (uint32_t)(row*HPITCH + cc*8)*2,
                           hsrc + (size_t)row*H_ + kc*512 + cc*8);
            }
            cp_commit();
        };

        issueH(0);
        issueH(1);
        cp_wait<1>();          // EB + chunk0 ready
        __syncthreads();
#pragma unroll
        for (int c = 0; c < 2; c++){
            if (c == 1){ cp_wait<0>(); __syncthreads(); }
            uint32_t aU = hU + (uint32_t)((c & 1)*64*HPITCH)*2;
            uint32_t bU = sbase + OFF_W + (uint32_t)(c*512)*2;

            uint32_t afr[2][4], bfr[2][4];
            ldsm4(afr[0][0],afr[0][1],afr[0][2],afr[0][3],
                  aU + (uint32_t)(arow*HPITCH + acol)*2);
            ldsm4(bfr[0][0],bfr[0][1],bfr[0][2],bfr[0][3],
                  bU + (uint32_t)(brow*WPITCH + bcol)*2);
#pragma unroll
            for (int i = 0; i < 32; i++){
                int cur = i & 1, nxt = cur ^ 1;
                if (i < 31){
                    int kk = (i+1)*16;
                    ldsm4(afr[nxt][0],afr[nxt][1],afr[nxt][2],afr[nxt][3],
                          aU + (uint32_t)(arow*HPITCH + kk + acol)*2);
                    ldsm4(bfr[nxt][0],bfr[nxt][1],bfr[nxt][2],bfr[nxt][3],
                          bU + (uint32_t)(brow*WPITCH + kk + bcol)*2);
                }
                mma16816(acc[0], afr[cur], bfr[cur][0], bfr[cur][1]);
                mma16816(acc[1], afr[cur], bfr[cur][2], bfr[cur][3]);
            }
        }

        // epilogue: add embg(smem) + gctx at fragment coords, write sGT
#pragma unroll
        for (int h = 0; h < 2; h++){
            int b = mi*16 + h*8 + rin;
#pragma unroll
            for (int nj = 0; nj < 2; nj++){
                int col = nh*16 + nj*8 + cin;
                float2 e = __half22float2(*(const __half2*)(sEB + b*40 + col));
                float v0 = acc[nj][h*2+0] + e.x + sGC[b*32 + col];
                float v1 = acc[nj][h*2+1] + e.y + sGC[b*32 + col + 1];
                sGT[b*36 + col]     = v0;
                sGT[b*36 + col + 1] = v1;
            }
        }
        __syncthreads();

        // cell: write h only (release set); keep hcat values in registers
        __half* hdst = g_hbuf[(t+1) & 1];
        __half hc_h[2], hc_c[2];
#pragma unroll
        for (int r2 = 0; r2 < 2; r2++){
            int e = tid + r2*256;
            int b = e >> 3, jj = e & 7;
            float* gp = sGT + b*36;
            float ig = sigf(gp[jj]);
            float fg = sigf(gp[8 + jj]);
            float gg = tanhf(gp[16 + jj]);
            float og = sigf(gp[24 + jj]);
            float cn = fg * sC[e] + ig * gg;
            float hn = og * tanhf(cn);
            sC[e] = cn;
            __half h16 = __float2half(hn);
            hc_h[r2] = h16;
            hc_c[r2] = __float2half(cn);
            if (t < T_-1) hdst[b*H_ + js0 + jj] = h16;
        }
        __syncthreads();

        if (t < T_-1){
            // arrival (release folds the h-write visibility; no threadfence)
            if (tid == 0){
                unsigned old;
                asm volatile("atom.release.gpu.global.add.u32 %0, [%1], 1;"
                             : "=r"(old) : "l"(&g_bar1[gidx*32]) : "memory");
                if (old == (unsigned)(16*(t+1) - 1)){
                    unsigned o2;
                    asm volatile("atom.acq_rel.gpu.global.add.u32 %0, [%1], 1;"
                                 : "=r"(o2) : "l"(&g_bar2) : "memory");
                }
            }
            // hcat history writes overlap the barrier wait
#pragma unroll
            for (int r2 = 0; r2 < 2; r2++){
                int e = tid + r2*256;
                int b = e >> 3, jj = e & 7;
                size_t hb = (size_t)(t*B_ + b)*(2*H_);
                g_hcat[hb + js0 + jj]      = hc_h[r2];
                g_hcat[hb + H_ + js0 + jj] = hc_c[r2];
            }
            if (tid == 0){
                unsigned tgt = 8u*(t+1);
                unsigned v;
                do {
                    asm volatile("ld.acquire.gpu.global.u32 %0, [%1];" : "=r"(v) : "l"(&g_bar2));
                } while (v < tgt);
            }
            __syncthreads();
        } else {
#pragma unroll
            for (int r2 = 0; r2 < 2; r2++){
                int e = tid + r2*256;
                int b = e >> 3, jj = e & 7;
                size_t hb = (size_t)(t*B_ + b)*(2*H_);
                g_hcat[hb + js0 + jj]      = hc_h[r2];
                g_hcat[hb + H_ + js0 + jj] = hc_c[r2];
            }
        }
    }
}

// ---------------- fp16 HMMA GEMM (CTA 128x128, warp 32x64, f32 acc) ----------------
#define KC 64
#define LDA 72
#define STAGES 3
#define STAGE_H (128*LDA)
#define HG_SMEM (STAGES*2*STAGE_H*2)   // 110592 bytes

template<int ACT, int OUT16>
__global__ __launch_bounds__(256,2) void hgemm(
    const __half* __restrict__ A, const __half* __restrict__ B,
    const float* __restrict__ bias,
    float* __restrict__ C, __half* __restrict__ C16,
    int ldc, int K)
{
    extern __shared__ __half sh[];
    uint32_t sAu = smem_u32(sh);
    uint32_t sBu = sAu + STAGES*STAGE_H*2;
    int tid = threadIdx.x;
    int lane = tid & 31, wid = tid >> 5;
    int wm = wid & 3, wn = wid >> 2;
    int m0 = blockIdx.x*128, n0 = blockIdx.y*128;
    const __half* Ab = A + (size_t)m0*K;
    const __half* Bb = B + (size_t)n0*K;
    int NKC = K / KC;

    int quad = lane >> 3, l7 = lane & 7;
    int arow = wm*32 + (quad & 1)*8 + l7;
    int acol = (quad >> 1)*8;
    int brow = wn*64 + (quad >> 1)*8 + l7;
    int bcol = (quad & 1)*8;

    float acc[2][8][4];
#pragma unroll
    for (int i=0;i<2;i++)
#pragma unroll
      for (int j=0;j<8;j++)
#pragma unroll
        for (int q=0;q<4;q++) acc[i][j][q]=0.f;

    auto issue = [&](int c){
        int s = c % STAGES;
        int k0 = c * KC;
        uint32_t da = sAu + (uint32_t)(s*STAGE_H)*2;
        uint32_t db = sBu + (uint32_t)(s*STAGE_H)*2;
#pragma unroll
        for (int i = 0; i < 4; i++){
            int q = i*256 + tid;
            int row = q >> 3, cc = (q & 7)*8;
            cp_async16(da + (uint32_t)(row*LDA + cc)*2, Ab + (size_t)row*K + k0 + cc);
            cp_async16(db + (uint32_t)(row*LDA + cc)*2, Bb + (size_t)row*K + k0 + cc);
        }
        cp_commit();
    };

    issue(0); issue(1);

    for (int c = 0; c < NKC; c++){
        if (c < NKC-1) cp_wait<1>(); else cp_wait<0>();
        __syncthreads();
        if (c + 2 < NKC) issue(c + 2);

        int s = c % STAGES;
        uint32_t ab = sAu + (uint32_t)(s*STAGE_H)*2;
        uint32_t bb = sBu + (uint32_t)(s*STAGE_H)*2;
#pragma unroll
        for (int kk = 0; kk < KC; kk += 16){
            uint32_t afr[2][4];
#pragma unroll
            for (int mi = 0; mi < 2; mi++)
                ldsm4(afr[mi][0], afr[mi][1], afr[mi][2], afr[mi][3],
                      ab + (uint32_t)((arow + mi*16)*LDA + kk + acol)*2);
#pragma unroll
            for (int nj = 0; nj < 4; nj++){
                uint32_t b0,b1,b2,b3;
                ldsm4(b0,b1,b2,b3,
                      bb + (uint32_t)((brow + nj*16)*LDA + kk + bcol)*2);
#pragma unroll
                for (int mi = 0; mi < 2; mi++){
                    mma16816(acc[mi][nj*2],   afr[mi], b0, b1);
                    mma16816(acc[mi][nj*2+1], afr[mi], b2, b3);
                }
            }
        }
    }
    __syncthreads();

    int rin = lane >> 2, cin = (lane & 3)*2;
#pragma unroll
    for (int mi = 0; mi < 2; mi++){
#pragma unroll
        for (int h = 0; h < 2; h++){
            size_t row = (size_t)(m0 + wm*32 + mi*16 + h*8 + rin);
#pragma unroll
            for (int nj = 0; nj < 8; nj++){
                int col = n0 + wn*64 + nj*8 + cin;
                float v0 = acc[mi][nj][h*2+0];
                float v1 = acc[mi][nj][h*2+1];
                if (bias){ v0 += bias[col]; v1 += bias[col+1]; }
                if (ACT == 1){ v0 = tanhf(v0); v1 = tanhf(v1); }
                if (OUT16){
                    __half2 hv; hv.x = __float2half(v0); hv.y = __float2half(v1);
                    *(__half2*)(C16 + row*(size_t)ldc + col) = hv;
                } else {
                    float2 f; f.x = v0; f.y = v1;
                    *(float2*)(C + row*(size_t)ldc + col) = f;
                }
            }
        }
    }
}

// ---------------- launch ----------------
extern "C" void kernel_launch(void* const* d_in, const int* in_sizes, int n_in,
                              void* d_out, int out_size) {
  const int*   seq     = (const int*)  d_in[0];
  const float* context = (const float*)d_in[1];
  const float* emb     = (const float*)d_in[2];
  const float* W_ih    = (const float*)d_in[3];
  const float* b_ih    = (const float*)d_in[4];
  const float* W_hh    = (const float*)d_in[5];
  const float* b_hh    = (const float*)d_in[6];
  const float* W_initS = (const float*)d_in[7];
  const float* b_initS = (const float*)d_in[8];
  const float* W_initC = (const float*)d_in[9];
  const float* b_initC = (const float*)d_in[10];
  const float* W_d1    = (const float*)d_in[11];
  const float* b_d1    = (const float*)d_in[12];
  const float* W_d2    = (const float*)d_in[13];
  const float* b_d2    = (const float*)d_in[14];
  float* out = (float*)d_out;

  void* p;
  cudaGetSymbolAddress(&p, g_xe);    __half* pxe   = (__half*)p;
  cudaGetSymbolAddress(&p, g_wihe);  __half* pwih  = (__half*)p;
  cudaGetSymbolAddress(&p, g_embg);  __half* pembg = (__half*)p;
  cudaGetSymbolAddress(&p, g_wd1);   __half* pw1   = (__half*)p;
  cudaGetSymbolAddress(&p, g_wd2);   __half* pw2   = (__half*)p;
  cudaGetSymbolAddress(&p, g_hcat);  __half* phc   = (__half*)p;
  cudaGetSymbolAddress(&p, g_hid);   __half* phi   = (__half*)p;

  cudaFuncSetAttribute((const void*)hgemm<0,0>, cudaFuncAttributeMaxDynamicSharedMemorySize, HG_SMEM);
  cudaFuncSetAttribute((const void*)hgemm<0,1>, cudaFuncAttributeMaxDynamicSharedMemorySize, HG_SMEM);
  cudaFuncSetAttribute((const void*)hgemm<1,1>, cudaFuncAttributeMaxDynamicSharedMemorySize, HG_SMEM);
  cudaFuncSetAttribute((const void*)rec_kernel, cudaFuncAttributeMaxDynamicSharedMemorySize, REC_SMEM);

  // one fused prep launch: embeddings + all weight conversions
  prep_kernel<<<M_ + FOURH + H_ + V_, 128>>>(seq, emb, W_ih, W_d1, W_d2);

  // fused init: h0 (fp16), c0, gctx + barrier reset
  init_gemm<<<96, 256>>>(context, W_initS, b_initS, W_initC, b_initC,
                         W_ih, b_ih, b_hh);

  // embg (fp16 out): [4096,512]x[512,4096]
  hgemm<0,1><<<dim3(M_/128, FOURH/128), 256, HG_SMEM>>>(
      pxe, pwih, nullptr, nullptr, pembg, FOURH, E_);

  // fused persistent recurrence
  rec_kernel<<<RC, 256, REC_SMEM>>>(W_hh);

  // d1: [4096,2048]x[2048,1024] -> fp16
  hgemm<1,1><<<dim3(M_/128, H_/128), 256, HG_SMEM>>>(
      phc, pw1, b_d1, nullptr, phi, H_, 2*H_);

  // d2: [4096,1024]x[1024,32000] -> fp32
  hgemm<0,0><<<dim3(M_/128, V_/128), 256, HG_SMEM>>>(
      phi, pw2, b_d2, out, nullptr, V_, H_);
}

// round 15
// speedup vs baseline: 1.0330x; 1.0330x over previous
#include <cuda_runtime.h>
#include <cuda_fp16.h>
#include <math.h>
#include <stdint.h>

#define T_ 64
#define B_ 64
#define V_ 32000
#define E_ 512
#define H_ 1024
#define CTX_ 1024
#define FOURH 4096
#define M_ (T_*B_)
#define RC 128

// ---------------- device scratch ----------------
__device__ __align__(256) float g_c[B_*H_];
__device__ __align__(256) float g_gctx[B_*FOURH];
__device__ __align__(256) unsigned g_bar1[8*32];
__device__ unsigned g_bar2;

__device__ __align__(256) __half g_embg[M_*FOURH];
__device__ __align__(256) __half g_hbuf[2][B_*H_];
__device__ __align__(256) __half g_xe[M_*E_];
__device__ __align__(256) __half g_wihe[FOURH*E_];
__device__ __align__(256) __half g_wd1[H_*2*H_];
__device__ __align__(256) __half g_wd2[(size_t)V_*H_];
__device__ __align__(256) __half g_hcat[M_*2*H_];
__device__ __align__(256) __half g_hid[M_*H_];

__device__ __forceinline__ float sigf(float x){ return 1.f/(1.f+__expf(-x)); }
__device__ __forceinline__ float tanhfast(float x){
    // tanh(x) = 1 - 2/(exp(2x)+1); exact saturation via inf/0
    float e = __expf(2.f*x);
    return 1.f - __fdividef(2.f, e + 1.f);
}

__device__ __forceinline__ uint32_t smem_u32(const void* p) {
    uint32_t a;
    asm("{ .reg .u64 t; cvta.to.shared.u64 t, %1; cvt.u32.u64 %0, t; }" : "=r"(a) : "l"(p));
    return a;
}
__device__ __forceinline__ void cp_async16(uint32_t dst, const void* src){
    asm volatile("cp.async.cg.shared.global [%0], [%1], 16;\n" :: "r"(dst), "l"(src));
}
__device__ __forceinline__ void cp_commit(){
    asm volatile("cp.async.commit_group;\n" ::: "memory");
}
template<int N> __device__ __forceinline__ void cp_wait(){
    asm volatile("cp.async.wait_group %0;\n" :: "n"(N) : "memory");
}
__device__ __forceinline__ void ldsm4(uint32_t& r0,uint32_t& r1,uint32_t& r2,uint32_t& r3,
                                      uint32_t addr){
    asm volatile("ldmatrix.sync.aligned.m8n8.x4.shared.b16 {%0,%1,%2,%3}, [%4];\n"
        : "=r"(r0),"=r"(r1),"=r"(r2),"=r"(r3) : "r"(addr));
}
__device__ __forceinline__ void mma16816(float* d, const uint32_t* a, uint32_t b0, uint32_t b1){
    asm volatile("mma.sync.aligned.m16n8k16.row.col.f32.f16.f16.f32 "
        "{%0,%1,%2,%3}, {%4,%5,%6,%7}, {%8,%9}, {%0,%1,%2,%3};\n"
        : "+f"(d[0]),"+f"(d[1]),"+f"(d[2]),"+f"(d[3])
        : "r"(a[0]),"r"(a[1]),"r"(a[2]),"r"(a[3]), "r"(b0),"r"(b1));
}

// ---- fused prep: embedding gather + all fp32->fp16 weight conversions ----
__global__ void prep_kernel(const int* __restrict__ seq, const float* __restrict__ emb,
                            const float* __restrict__ W_ih, const float* __restrict__ W_d1,
                            const float* __restrict__ W_d2){
    int bid = blockIdx.x;
    const float* src; int cols; __half* dst; size_t drow;
    if (bid < M_){
        int tok = __ldg(seq + bid);
        src = emb + (size_t)tok*E_; cols = E_;
        dst = g_xe; drow = (size_t)bid*E_;
    } else if (bid < M_ + FOURH){
        int r = bid - M_;
        src = W_ih + (size_t)r*(E_+CTX_) + CTX_; cols = E_;
        dst = g_wihe; drow = (size_t)r*E_;
    } else if (bid < M_ + FOURH + H_){
        int r = bid - M_ - FOURH;
        src = W_d1 + (size_t)r*(2*H_); cols = 2*H_;
        dst = g_wd1; drow = (size_t)r*(2*H_);
    } else {
        int r = bid - M_ - FOURH - H_;
        src = W_d2 + (size_t)r*H_; cols = H_;
        dst = g_wd2; drow = (size_t)r*H_;
    }
    const float4* s = (const float4*)src;
    for (int c4 = threadIdx.x; c4*4 < cols; c4 += blockDim.x){
        float4 v = s[c4];
        __half2 p0, p1;
        p0.x = __float2half(v.x); p0.y = __float2half(v.y);
        p1.x = __float2half(v.z); p1.y = __float2half(v.w);
        *(__half2*)(dst + drow + c4*4)     = p0;
        *(__half2*)(dst + drow + c4*4 + 2) = p1;
    }
}

// ---------------- fused init GEMM: h0, c0, gctx in one launch ----------------
__global__ __launch_bounds__(256) void init_gemm(
    const float* __restrict__ A,
    const float* __restrict__ W_initS, const float* __restrict__ b_initS,
    const float* __restrict__ W_initC, const float* __restrict__ b_initC,
    const float* __restrict__ W_ih,    const float* __restrict__ b_ih,
    const float* __restrict__ b_hh)
{
  int tid = threadIdx.x;
  int ny = blockIdx.x;
  if (ny == 0 && tid < 8) g_bar1[tid*32] = 0u;
  if (ny == 0 && tid == 0) g_bar2 = 0u;

  const float* W; int ldw; int cls; int nbase;
  if (ny < 16)      { W = W_initS + (size_t)ny*64*CTX_;           ldw = CTX_;      cls = 0; nbase = ny*64; }
  else if (ny < 32) { W = W_initC + (size_t)(ny-16)*64*CTX_;      ldw = CTX_;      cls = 1; nbase = (ny-16)*64; }
  else              { W = W_ih   + (size_t)(ny-32)*64*(E_+CTX_);  ldw = E_+CTX_;   cls = 2; nbase = (ny-32)*64; }

  __shared__ __align__(16) float As[16][68];
  __shared__ __align__(16) float Ws[16][68];
  int r = tid>>2, c4 = tid&3;
  int tx = tid&15, ty = tid>>4;
  float acc[4][4] = {};
  for (int k0=0;k0<CTX_;k0+=16){
    float4 av = *(const float4*)(A + (size_t)r*CTX_ + k0 + c4*4);
    float4 wv = *(const float4*)(W + (size_t)r*ldw + k0 + c4*4);
    As[c4*4+0][r]=av.x; As[c4*4+1][r]=av.y; As[c4*4+2][r]=av.z; As[c4*4+3][r]=av.w;
    Ws[c4*4+0][r]=wv.x; Ws[c4*4+1][r]=wv.y; Ws[c4*4+2][r]=wv.z; Ws[c4*4+3][r]=wv.w;
    __syncthreads();
#pragma unroll
    for (int kk=0;kk<16;kk++){
      float4 a = *(const float4*)&As[kk][ty*4];
      float4 w = *(const float4*)&Ws[kk][tx*4];
      float aa[4]={a.x,a.y,a.z,a.w}, ww[4]={w.x,w.y,w.z,w.w};
#pragma unroll
      for (int i=0;i<4;i++)
#pragma unroll
        for (int j=0;j<4;j++) acc[i][j] += aa[i]*ww[j];
    }
    __syncthreads();
  }
#pragma unroll
  for (int i=0;i<4;i++){
    int m = ty*4 + i;
#pragma unroll
    for (int j=0;j<4;j++){
      int n = nbase + tx*4 + j;
      float v = acc[i][j];
      if (cls == 0){
        v = tanhfast(v + b_initS[n]);
        g_hbuf[0][m*H_ + n] = __float2half(v);
      } else if (cls == 1){
        v = tanhfast(v + b_initC[n]);
        g_c[m*H_ + n] = v;
      } else {
        g_gctx[m*FOURH + n] = v + b_ih[n] + b_hh[n];
      }
    }
  }
}

// ---------------- persistent recurrence kernel (R13 version + tanhfast) ----------------
#define WPITCH 1032
#define HPITCH 520
#define OFF_W   0
#define OFF_H   (32*WPITCH*2)
#define OFF_GT  (OFF_H + 2*64*HPITCH*2)
#define OFF_GC  (OFF_GT + 64*36*4)
#define OFF_C   (OFF_GC + 64*32*4)
#define OFF_EB  (OFF_C + 512*4)
#define REC_SMEM (OFF_EB + 64*40*2)

__device__ __forceinline__ void gbar_sync(int step){
    __syncthreads();
    if (threadIdx.x == 0){
        __threadfence();
        int g = blockIdx.x & 7;
        unsigned old = atomicAdd(&g_bar1[g*32], 1u);
        if (old == (unsigned)(16*(step+1) - 1))
            atomicAdd(&g_bar2, 1u);
        unsigned tgt = (unsigned)(8*(step+1));
        for (;;){
            unsigned v;
            asm volatile("ld.acquire.gpu.global.u32 %0, [%1];" : "=r"(v) : "l"(&g_bar2));
            if (v >= tgt) break;
            __nanosleep(64);
        }
    }
    __syncthreads();
}

__global__ __launch_bounds__(256,1) void rec_kernel(const float* __restrict__ W_hh){
    extern __shared__ char sm[];
    uint32_t sbase = smem_u32(sm);
    float*  sGT = (float*) (sm + OFF_GT);
    float*  sGC = (float*) (sm + OFF_GC);
    float*  sC  = (float*) (sm + OFF_C);
    __half* sEB = (__half*)(sm + OFF_EB);
    uint32_t hU = sbase + OFF_H;
    uint32_t ebU = sbase + OFF_EB;

    int tid = threadIdx.x;
    int lane = tid & 31, wid = tid >> 5;
    int s = blockIdx.x;
    int js0 = s * 8;

    // W_hh slice: load fp32, convert, store to smem
    for (int q = tid; q < 4096; q += 256){
        int row = q >> 7, cc = q & 127;
        int grow = (row >> 3)*H_ + js0 + (row & 7);
        const float4* src = (const float4*)(W_hh + (size_t)grow*H_ + cc*8);
        float4 v0 = src[0], v1 = src[1];
        __half h[8];
        h[0]=__float2half(v0.x); h[1]=__float2half(v0.y);
        h[2]=__float2half(v0.z); h[3]=__float2half(v0.w);
        h[4]=__float2half(v1.x); h[5]=__float2half(v1.y);
        h[6]=__float2half(v1.z); h[7]=__float2half(v1.w);
        *(uint4*)(sm + OFF_W + (size_t)(row*WPITCH + cc*8)*2) = *(uint4*)h;
    }
    for (int e = tid; e < 2048; e += 256){
        int b = e >> 5, n = e & 31;
        sGC[b*32 + n] = g_gctx[b*FOURH + (n>>3)*H_ + js0 + (n&7)];
    }
    for (int e = tid; e < 512; e += 256)
        sC[e] = g_c[(e>>3)*H_ + js0 + (e&7)];
    __syncthreads();

    int quad = lane >> 3, l7 = lane & 7;
    int mi = wid & 3, nh = wid >> 2;
    int arow = mi*16 + (quad & 1)*8 + l7;
    int acol = (quad >> 1)*8;
    int brow = nh*16 + (quad >> 1)*8 + l7;
    int bcol = (quad & 1)*8;
    int rin = lane >> 2, cin = (lane & 3)*2;

    int pb = tid >> 2, pg = tid & 3;

    for (int t = 0; t < T_; t++){
        const __half* hsrc = g_hbuf[t & 1];

        float acc[2][4];
#pragma unroll
        for (int a=0;a<2;a++)
#pragma unroll
          for (int q=0;q<4;q++) acc[a][q]=0.f;

        // prefetch embg strip for this step (group 0)
        cp_async16(ebU + (uint32_t)(pb*40 + pg*8)*2,
                   g_embg + ((size_t)(t*B_ + pb))*FOURH + pg*H_ + js0);
        cp_commit();

        auto issueH = [&](int kc){
            uint32_t dU = hU + (uint32_t)((kc & 1)*64*HPITCH)*2;
#pragma unroll
            for (int i = 0; i < 16; i++){
                int q = i*256 + tid;
                int row = q >> 6, cc = q & 63;
                cp_async16(dU + (uint32_t)(row*HPITCH + cc*8)*2,
                           hsrc + (size_t)row*H_ + kc*512 + cc*8);
            }
            cp_commit();
        };

        issueH(0);
#pragma unroll
        for (int c = 0; c < 2; c++){
            if (c == 0){ issueH(1); cp_wait<1>(); }
            else       { cp_wait<0>(); }
            __syncthreads();
            uint32_t aU = hU + (uint32_t)((c & 1)*64*HPITCH)*2;
            uint32_t bU = sbase + OFF_W + (uint32_t)(c*512)*2;

            uint32_t afr[2][4], bfr[2][4];
            ldsm4(afr[0][0],afr[0][1],afr[0][2],afr[0][3],
                  aU + (uint32_t)(arow*HPITCH + acol)*2);
            ldsm4(bfr[0][0],bfr[0][1],bfr[0][2],bfr[0][3],
                  bU + (uint32_t)(brow*WPITCH + bcol)*2);
#pragma unroll
            for (int i = 0; i < 32; i++){
                int cur = i & 1, nxt = cur ^ 1;
                if (i < 31){
                    int kk = (i+1)*16;
                    ldsm4(afr[nxt][0],afr[nxt][1],afr[nxt][2],afr[nxt][3],
                          aU + (uint32_t)(arow*HPITCH + kk + acol)*2);
                    ldsm4(bfr[nxt][0],bfr[nxt][1],bfr[nxt][2],bfr[nxt][3],
                          bU + (uint32_t)(brow*WPITCH + kk + bcol)*2);
                }
                mma16816(acc[0], afr[cur], bfr[cur][0], bfr[cur][1]);
                mma16816(acc[1], afr[cur], bfr[cur][2], bfr[cur][3]);
            }
            __syncthreads();
        }

#pragma unroll
        for (int h = 0; h < 2; h++){
            int b = mi*16 + h*8 + rin;
#pragma unroll
            for (int nj = 0; nj < 2; nj++){
                int col = nh*16 + nj*8 + cin;
                float2 e = __half22float2(*(const __half2*)(sEB + b*40 + col));
                float v0 = acc[nj][h*2+0] + e.x + sGC[b*32 + col];
                float v1 = acc[nj][h*2+1] + e.y + sGC[b*32 + col + 1];
                sGT[b*36 + col]     = v0;
                sGT[b*36 + col + 1] = v1;
            }
        }
        __syncthreads();

        __half* hdst = g_hbuf[(t+1) & 1];
        for (int e = tid; e < 512; e += 256){
            int b = e >> 3, jj = e & 7;
            float* gp = sGT + b*36;
            float ig = sigf(gp[jj]);
            float fg = sigf(gp[8 + jj]);
            float gg = tanhfast(gp[16 + jj]);
            float og = sigf(gp[24 + jj]);
            float cn = fg * sC[e] + ig * gg;
            float hn = og * tanhfast(cn);
            sC[e] = cn;
            __half h16 = __float2half(hn);
            if (t < T_-1) hdst[b*H_ + js0 + jj] = h16;
            size_t hb = (size_t)(t*B_ + b)*(2*H_);
            g_hcat[hb + js0 + jj]      = h16;
            g_hcat[hb + H_ + js0 + jj] = __float2half(cn);
        }
        if (t < T_-1) gbar_sync(t);
    }
}

// ---------------- fp16 HMMA GEMM (CTA 128x128, warp 32x64, f32 acc) ----------------
#define KC 64
#define LDA 72
#define STAGES 3
#define STAGE_H (128*LDA)
#define HG_SMEM (STAGES*2*STAGE_H*2)   // 110592 bytes

template<int ACT, int OUT16>
__global__ __launch_bounds__(256,2) void hgemm(
    const __half* __restrict__ A, const __half* __restrict__ B,
    const float* __restrict__ bias,
    float* __restrict__ C, __half* __restrict__ C16,
    int ldc, int K)
{
    extern __shared__ __half sh[];
    uint32_t sAu = smem_u32(sh);
    uint32_t sBu = sAu + STAGES*STAGE_H*2;
    int tid = threadIdx.x;
    int lane = tid & 31, wid = tid >> 5;
    int wm = wid & 3, wn = wid >> 2;
    int m0 = blockIdx.x*128, n0 = blockIdx.y*128;
    const __half* Ab = A + (size_t)m0*K;
    const __half* Bb = B + (size_t)n0*K;
    int NKC = K / KC;

    int quad = lane >> 3, l7 = lane & 7;
    int arow = wm*32 + (quad & 1)*8 + l7;
    int acol = (quad >> 1)*8;
    int brow = wn*64 + (quad >> 1)*8 + l7;
    int bcol = (quad & 1)*8;

    float acc[2][8][4];
#pragma unroll
    for (int i=0;i<2;i++)
#pragma unroll
      for (int j=0;j<8;j++)
#pragma unroll
        for (int q=0;q<4;q++) acc[i][j][q]=0.f;

    auto issue = [&](int c){
        int s = c % STAGES;
        int k0 = c * KC;
        uint32_t da = sAu + (uint32_t)(s*STAGE_H)*2;
        uint32_t db = sBu + (uint32_t)(s*STAGE_H)*2;
#pragma unroll
        for (int i = 0; i < 4; i++){
            int q = i*256 + tid;
            int row = q >> 3, cc = (q & 7)*8;
            cp_async16(da + (uint32_t)(row*LDA + cc)*2, Ab + (size_t)row*K + k0 + cc);
            cp_async16(db + (uint32_t)(row*LDA + cc)*2, Bb + (size_t)row*K + k0 + cc);
        }
        cp_commit();
    };

    issue(0); issue(1);

    for (int c = 0; c < NKC; c++){
        if (c < NKC-1) cp_wait<1>(); else cp_wait<0>();
        __syncthreads();
        if (c + 2 < NKC) issue(c + 2);

        int s = c % STAGES;
        uint32_t ab = sAu + (uint32_t)(s*STAGE_H)*2;
        uint32_t bb = sBu + (uint32_t)(s*STAGE_H)*2;
#pragma unroll
        for (int kk = 0; kk < KC; kk += 16){
            uint32_t afr[2][4];
#pragma unroll
            for (int mi = 0; mi < 2; mi++)
                ldsm4(afr[mi][0], afr[mi][1], afr[mi][2], afr[mi][3],
                      ab + (uint32_t)((arow + mi*16)*LDA + kk + acol)*2);
#pragma unroll
            for (int nj = 0; nj < 4; nj++){
                uint32_t b0,b1,b2,b3;
                ldsm4(b0,b1,b2,b3,
                      bb + (uint32_t)((brow + nj*16)*LDA + kk + bcol)*2);
#pragma unroll
                for (int mi = 0; mi < 2; mi++){
                    mma16816(acc[mi][nj*2],   afr[mi], b0, b1);
                    mma16816(acc[mi][nj*2+1], afr[mi], b2, b3);
                }
            }
        }
    }
    __syncthreads();

    int rin = lane >> 2, cin = (lane & 3)*2;
#pragma unroll
    for (int mi = 0; mi < 2; mi++){
#pragma unroll
        for (int h = 0; h < 2; h++){
            size_t row = (size_t)(m0 + wm*32 + mi*16 + h*8 + rin);
#pragma unroll
            for (int nj = 0; nj < 8; nj++){
                int col = n0 + wn*64 + nj*8 + cin;
                float v0 = acc[mi][nj][h*2+0];
                float v1 = acc[mi][nj][h*2+1];
                if (bias){ v0 += bias[col]; v1 += bias[col+1]; }
                if (ACT == 1){ v0 = tanhfast(v0); v1 = tanhfast(v1); }
                if (OUT16){
                    __half2 hv; hv.x = __float2half(v0); hv.y = __float2half(v1);
                    *(__half2*)(C16 + row*(size_t)ldc + col) = hv;
                } else {
                    float2 f; f.x = v0; f.y = v1;
                    *(float2*)(C + row*(size_t)ldc + col) = f;
                }
            }
        }
    }
}

// ---------------- launch ----------------
extern "C" void kernel_launch(void* const* d_in, const int* in_sizes, int n_in,
                              void* d_out, int out_size) {
  const int*   seq     = (const int*)  d_in[0];
  const float* context = (const float*)d_in[1];
  const float* emb     = (const float*)d_in[2];
  const float* W_ih    = (const float*)d_in[3];
  const float* b_ih    = (const float*)d_in[4];
  const float* W_hh    = (const float*)d_in[5];
  const float* b_hh    = (const float*)d_in[6];
  const float* W_initS = (const float*)d_in[7];
  const float* b_initS = (const float*)d_in[8];
  const float* W_initC = (const float*)d_in[9];
  const float* b_initC = (const float*)d_in[10];
  const float* W_d1    = (const float*)d_in[11];
  const float* b_d1    = (const float*)d_in[12];
  const float* W_d2    = (const float*)d_in[13];
  const float* b_d2    = (const float*)d_in[14];
  float* out = (float*)d_out;

  void* p;
  cudaGetSymbolAddress(&p, g_xe);    __half* pxe   = (__half*)p;
  cudaGetSymbolAddress(&p, g_wihe);  __half* pwih  = (__half*)p;
  cudaGetSymbolAddress(&p, g_embg);  __half* pembg = (__half*)p;
  cudaGetSymbolAddress(&p, g_wd1);   __half* pw1   = (__half*)p;
  cudaGetSymbolAddress(&p, g_wd2);   __half* pw2   = (__half*)p;
  cudaGetSymbolAddress(&p, g_hcat);  __half* phc   = (__half*)p;
  cudaGetSymbolAddress(&p, g_hid);   __half* phi   = (__half*)p;

  cudaFuncSetAttribute((const void*)hgemm<0,0>, cudaFuncAttributeMaxDynamicSharedMemorySize, HG_SMEM);
  cudaFuncSetAttribute((const void*)hgemm<0,1>, cudaFuncAttributeMaxDynamicSharedMemorySize, HG_SMEM);
  cudaFuncSetAttribute((const void*)hgemm<1,1>, cudaFuncAttributeMaxDynamicSharedMemorySize, HG_SMEM);
  cudaFuncSetAttribute((const void*)rec_kernel, cudaFuncAttributeMaxDynamicSharedMemorySize, REC_SMEM);

  // one fused prep launch: embeddings + all weight conversions
  prep_kernel<<<M_ + FOURH + H_ + V_, 128>>>(seq, emb, W_ih, W_d1, W_d2);

  // fused init: h0 (fp16), c0, gctx + barrier reset
  init_gemm<<<96, 256>>>(context, W_initS, b_initS, W_initC, b_initC,
                         W_ih, b_ih, b_hh);

  // embg (fp16 out): [4096,512]x[512,4096]
  hgemm<0,1><<<dim3(M_/128, FOURH/128), 256, HG_SMEM>>>(
      pxe, pwih, nullptr, nullptr, pembg, FOURH, E_);

  // fused persistent recurrence (W_hh converted in-kernel)
  rec_kernel<<<RC, 256, REC_SMEM>>>(W_hh);

  // d1: [4096,2048]x[2048,1024] -> fp16 (f32 acc)
  hgemm<1,1><<<dim3(M_/128, H_/128), 256, HG_SMEM>>>(
      phc, pw1, b_d1, nullptr, phi, H_, 2*H_);

  // d2: [4096,1024]x[1024,32000] -> fp32 (f32 acc, plain stores)
  hgemm<0,0><<<dim3(M_/128, V_/128), 256, HG_SMEM>>>(
      phi, pw2, b_d2, out, nullptr, V_, H_);
}